// round 1
// baseline (speedup 1.0000x reference)
#include <cuda_runtime.h>
#include <cstdint>

#define N_NODES 50000
#define DIM 128

// Scratch (static device globals — no allocation at runtime)
__device__ float g_agg[(size_t)N_NODES * DIM];   // weighted neighbor sums
__device__ float g_deg[N_NODES];                 // in-degree (edge weight count = 1.0 per edge)
__device__ float g_h1[(size_t)N_NODES * DIM];    // hidden activations after layer 1

// ---------------------------------------------------------------------------
// zero: grid-stride float4 clear
// ---------------------------------------------------------------------------
__global__ void zero_kernel(float4* __restrict__ p, int n4) {
    int i = blockIdx.x * blockDim.x + threadIdx.x;
    float4 z = make_float4(0.f, 0.f, 0.f, 0.f);
    for (; i < n4; i += gridDim.x * blockDim.x) p[i] = z;
}

// ---------------------------------------------------------------------------
// edge scatter: one warp per edge.
//   lane l handles dims [4l, 4l+4):  agg[dst] += w * h[src]   (vector red)
//   lane 0 optionally bumps deg[dst].
// ---------------------------------------------------------------------------
__global__ void edge_kernel(const float* __restrict__ h,
                            const int*   __restrict__ src,
                            const int*   __restrict__ dst,
                            const float* __restrict__ wt,
                            float*       __restrict__ agg,
                            float*       __restrict__ deg,
                            int E, int update_deg)
{
    int warp = (blockIdx.x * blockDim.x + threadIdx.x) >> 5;
    int lane = threadIdx.x & 31;
    if (warp >= E) return;

    int s = src[warp];
    int d = dst[warp];
    float w = wt[warp];

    const float4* hv = (const float4*)(h + (size_t)s * DIM);
    float4 v = hv[lane];
    v.x *= w; v.y *= w; v.z *= w; v.w *= w;

    float* ap = agg + (size_t)d * DIM + lane * 4;
    asm volatile("red.global.add.v4.f32 [%0], {%1, %2, %3, %4};"
                 :: "l"(ap), "f"(v.x), "f"(v.y), "f"(v.z), "f"(v.w)
                 : "memory");

    if (update_deg && lane == 0)
        atomicAdd(deg + d, 1.0f);
}

// ---------------------------------------------------------------------------
// Fused SAGE GEMM:
//   out[r, j] = sum_k h[r,k]*Ws[j,k] + (agg[r,k]/max(deg[r],1))*Wn[j,k] + b[j]
// i.e. one GEMM with K = 256 (concat of self and neighbor halves).
// CTA tile: 64 rows x 128 cols. 256 threads, each computes 8 rows x 4 cols.
// K is chunked by 32; the small 128x128 weight matrices stay hot in L2, so
// re-streaming W chunks per CTA is cheap (~100 MB of L2 traffic total).
// ---------------------------------------------------------------------------
#define TILE_ROWS 64
#define KC 32

__global__ __launch_bounds__(256, 2)
void sage_gemm(const float* __restrict__ Aself,
               const float* __restrict__ Aneigh,
               const float* __restrict__ deg,
               const float* __restrict__ Ws,
               const float* __restrict__ Wn,
               const float* __restrict__ bias,
               float*       __restrict__ out,
               int nrows, int do_relu)
{
    __shared__ float As[TILE_ROWS][KC + 4];   // pad 36: conflict-free bcast reads, aligned f4 stores
    __shared__ float Wt[KC][DIM + 1];         // pad 129: conflict-free scalar reads
    __shared__ float rdeg_s[TILE_ROWS];
    __shared__ float bs[DIM];

    int tid = threadIdx.x;
    int tx = tid & 31;        // output-column lane
    int ty = tid >> 5;        // row-group 0..7 (8 rows each)
    int rowbase = blockIdx.x * TILE_ROWS;

    if (tid < TILE_ROWS) {
        int r = rowbase + tid;
        float dg = (r < nrows) ? deg[r] : 1.0f;
        rdeg_s[tid] = 1.0f / fmaxf(dg, 1.0f);
    }
    if (tid < DIM) bs[tid] = bias[tid];

    float acc[8][4];
#pragma unroll
    for (int i = 0; i < 8; i++)
#pragma unroll
        for (int m = 0; m < 4; m++) acc[i][m] = 0.f;

    // A-chunk load mapping: 4 threads per row, 8 floats (2x float4) per thread
    int lrow = tid >> 2;            // 0..63
    int lcol = (tid & 3) * 8;       // 0,8,16,24
    int grow = rowbase + lrow;
    if (grow > nrows - 1) grow = nrows - 1;   // clamp (results discarded on store)

    for (int kc = 0; kc < 2 * DIM; kc += KC) {
        __syncthreads();

        // ---- load W chunk (transposed): Wt[kk][j] = W[j][kb+kk] ----
        {
            const float* W = (kc < DIM) ? Ws : Wn;
            int kb = kc & (DIM - 1);
#pragma unroll
            for (int it = 0; it < (KC * DIM) / 256; it++) {
                int idx = tid + it * 256;       // 0..4095
                int kk = idx & (KC - 1);
                int j  = idx >> 5;
                Wt[kk][j] = W[j * DIM + kb + kk];   // coalesced: warp covers one j row
            }
        }

        // ---- load A chunk (self half, or scaled neighbor half) ----
        {
            float4 v0, v1;
            if (kc < DIM) {
                const float4* p = (const float4*)(Aself + (size_t)grow * DIM + kc + lcol);
                v0 = p[0]; v1 = p[1];
            } else {
                const float4* p = (const float4*)(Aneigh + (size_t)grow * DIM + (kc - DIM) + lcol);
                v0 = p[0]; v1 = p[1];
                float rd = rdeg_s[lrow];
                v0.x *= rd; v0.y *= rd; v0.z *= rd; v0.w *= rd;
                v1.x *= rd; v1.y *= rd; v1.z *= rd; v1.w *= rd;
            }
            *(float4*)&As[lrow][lcol]     = v0;
            *(float4*)&As[lrow][lcol + 4] = v1;
        }
        __syncthreads();

        // ---- inner product: 32 FFMA per kk per thread ----
#pragma unroll
        for (int kk = 0; kk < KC; kk++) {
            float w[4], a[8];
#pragma unroll
            for (int m = 0; m < 4; m++) w[m] = Wt[kk][tx + 32 * m];
#pragma unroll
            for (int i = 0; i < 8; i++) a[i] = As[ty * 8 + i][kk];
#pragma unroll
            for (int i = 0; i < 8; i++)
#pragma unroll
                for (int m = 0; m < 4; m++)
                    acc[i][m] += a[i] * w[m];
        }
    }

    // ---- epilogue: bias (+ relu), coalesced stores ----
#pragma unroll
    for (int i = 0; i < 8; i++) {
        int r = rowbase + ty * 8 + i;
        if (r < nrows) {
#pragma unroll
            for (int m = 0; m < 4; m++) {
                int j = tx + 32 * m;
                float v = acc[i][m] + bs[j];
                if (do_relu) v = fmaxf(v, 0.f);
                out[(size_t)r * DIM + j] = v;
            }
        }
    }
}

// ---------------------------------------------------------------------------
extern "C" void kernel_launch(void* const* d_in, const int* in_sizes, int n_in,
                              void* d_out, int out_size)
{
    const float* x   = (const float*)d_in[0];
    const int*   src = (const int*)  d_in[1];
    const int*   dst = (const int*)  d_in[2];
    const float* wt  = (const float*)d_in[3];
    const float* Ws1 = (const float*)d_in[4];
    const float* Wn1 = (const float*)d_in[5];
    const float* b1  = (const float*)d_in[6];
    const float* Ws2 = (const float*)d_in[7];
    const float* Wn2 = (const float*)d_in[8];
    const float* b2  = (const float*)d_in[9];
    float* out = (float*)d_out;

    int E = in_sizes[1];

    float *agg, *deg, *h1;
    cudaGetSymbolAddress((void**)&agg, g_agg);
    cudaGetSymbolAddress((void**)&deg, g_deg);
    cudaGetSymbolAddress((void**)&h1,  g_h1);

    const int AGG4 = (N_NODES * DIM) / 4;
    const int DEG4 = N_NODES / 4;
    int eblocks = (E + 7) / 8;                 // 8 warps / block, 1 warp / edge
    int gblocks = (N_NODES + TILE_ROWS - 1) / TILE_ROWS;

    // ---- layer 1 ----
    zero_kernel<<<1024, 256>>>((float4*)agg, AGG4);
    zero_kernel<<<64,   256>>>((float4*)deg, DEG4);
    edge_kernel<<<eblocks, 256>>>(x, src, dst, wt, agg, deg, E, 1);
    sage_gemm<<<gblocks, 256>>>(x, agg, deg, Ws1, Wn1, b1, h1, N_NODES, 1);

    // ---- layer 2 (deg unchanged: same dst) ----
    zero_kernel<<<1024, 256>>>((float4*)agg, AGG4);
    edge_kernel<<<eblocks, 256>>>(h1, src, dst, wt, agg, deg, E, 0);
    sage_gemm<<<gblocks, 256>>>(h1, agg, deg, Ws2, Wn2, b2, out, N_NODES, 0);
}